// round 3
// baseline (speedup 1.0000x reference)
#include <cuda_runtime.h>
#include <cuda_fp16.h>

#define NN   50000
#define EE   800000
#define EPAD 850000   // E + N self loops
#define IN1  192
#define C1   256

// ---------------- scratch (device globals; no runtime allocation) ----------------
__device__ float  g_x  [NN * IN1];   // concat(high, elu(emb))
__device__ __half g_h1h[NN * C1];    // layer-1 pre-aggregation features (fp16)
__device__ float  g_as1[NN * 8];
__device__ float  g_ad1[NN * 8];
__device__ float  g_ea [(size_t)EPAD * 8];  // per-edge softmax numerators (unnormalized)
__device__ float  g_h2 [NN * 8];     // layer-2 features
__device__ float  g_a2s[NN];
__device__ float  g_a2d[NN];
__device__ int    g_cnt[NN];         // degree counts, then scatter cursor
__device__ int    g_off[NN + 1];     // CSR offsets (by destination)
__device__ int    g_csr[EPAD];       // source index per CSR slot

__device__ __forceinline__ unsigned long long dup_f32(float f) {
    unsigned int u = __float_as_uint(f);
    return ((unsigned long long)u << 32) | (unsigned long long)u;
}

// ---------------- launch 1: emb = elu(low@W_emb + b), x = [high | emb]; zero g_cnt ----------------
__global__ void k_emb(const float* __restrict__ high, const float* __restrict__ low,
                      const float* __restrict__ Wemb, const float* __restrict__ bemb) {
    __shared__ float ls[2][32];
    int n = blockIdx.x * 2 + threadIdx.y;
    int c = threadIdx.x;
    int gt = n * 192 + c;
    if (gt < NN) g_cnt[gt] = 0;
    if (c < 32) ls[threadIdx.y][c] = low[n * 32 + c];
    __syncthreads();
    if (c < 128) {
        g_x[n * IN1 + c] = high[n * 128 + c];
    } else {
        int j = c - 128;
        float s = bemb[j];
#pragma unroll
        for (int k = 0; k < 32; k++) s += ls[threadIdx.y][k] * Wemb[k * 64 + j];
        g_x[n * IN1 + c] = s > 0.f ? s : expm1f(s);
    }
}

// ---------------- launch 2: per-destination degree count ----------------
__global__ void k_cnt_edges(const int* __restrict__ ei) {
    int e = blockIdx.x * blockDim.x + threadIdx.x;
    if (e < EE) atomicAdd(&g_cnt[ei[EE + e]], 1);
}

// ---------------- launch 3: scan -> g_off; also place self-loop, set cursor ----------------
__global__ void k_scan() {
    __shared__ int sums[1024];
    int t = threadIdx.x;
    const int CH = (NN + 1023) / 1024;
    int base = t * CH;
    int s = 0;
    for (int i = 0; i < CH; i++) { int idx = base + i; if (idx < NN) s += g_cnt[idx] + 1; }
    sums[t] = s;
    __syncthreads();
    for (int off = 1; off < 1024; off <<= 1) {
        int v = (t >= off) ? sums[t - off] : 0;
        __syncthreads();
        sums[t] += v;
        __syncthreads();
    }
    int run = sums[t] - s;
    for (int i = 0; i < CH; i++) {
        int idx = base + i;
        if (idx < NN) {
            int c = g_cnt[idx] + 1;       // +1 self loop
            g_off[idx] = run;
            g_csr[run] = idx;             // self loop in slot 0 of segment
            g_cnt[idx] = run + 1;         // scatter cursor (after self loop)
            run += c;
        }
    }
    if (t == 1023) g_off[NN] = sums[1023];
}

// ---------------- launch 4 (ncu target): h1 = x @ W1 with FFMA2, fused attention epilogue ----------------
__global__ void __launch_bounds__(128) k_gemm(const float* __restrict__ W1,
                                              const float* __restrict__ a_s,
                                              const float* __restrict__ a_d) {
    __shared__ float As[16][128];                       // [k][m]
    __shared__ unsigned long long Bs2[16][8][16];       // [k][j][tx] duplicated pairs
    int bm = blockIdx.x * 128, bn = blockIdx.y * 128;
    int tid = threadIdx.x;
    int tx = tid & 15, ty = tid >> 4;

    unsigned long long acc2[8][8];
#pragma unroll
    for (int i = 0; i < 8; i++)
#pragma unroll
        for (int j = 0; j < 8; j++) acc2[i][j] = 0ull;

    float4 pa[4], pb[4];
    // prefetch tile 0
#pragma unroll
    for (int it = 0; it < 4; it++) {
        int idx = tid + it * 128;
        int r = idx >> 2, c4 = idx & 3;
        int m = bm + r;
        pa[it] = make_float4(0.f, 0.f, 0.f, 0.f);
        if (m < NN) pa[it] = *(const float4*)&g_x[m * IN1 + c4 * 4];
        int rb = idx >> 5, cb = idx & 31;
        pb[it] = *(const float4*)&W1[rb * C1 + bn + cb * 4];
    }

    for (int k0 = 0; k0 < IN1; k0 += 16) {
        // commit prefetched tile to smem
#pragma unroll
        for (int it = 0; it < 4; it++) {
            int idx = tid + it * 128;
            int r = idx >> 2, c4 = idx & 3;
            As[c4 * 4 + 0][r] = pa[it].x; As[c4 * 4 + 1][r] = pa[it].y;
            As[c4 * 4 + 2][r] = pa[it].z; As[c4 * 4 + 3][r] = pa[it].w;
            int rb = idx >> 5, cb = idx & 31;
            int c = cb * 4;
            Bs2[rb][(c + 0) & 7][(c + 0) >> 3] = dup_f32(pb[it].x);
            Bs2[rb][(c + 1) & 7][(c + 1) >> 3] = dup_f32(pb[it].y);
            Bs2[rb][(c + 2) & 7][(c + 2) >> 3] = dup_f32(pb[it].z);
            Bs2[rb][(c + 3) & 7][(c + 3) >> 3] = dup_f32(pb[it].w);
        }
        __syncthreads();
        // issue next tile's global loads
        if (k0 + 16 < IN1) {
#pragma unroll
            for (int it = 0; it < 4; it++) {
                int idx = tid + it * 128;
                int r = idx >> 2, c4 = idx & 3;
                int m = bm + r;
                pa[it] = make_float4(0.f, 0.f, 0.f, 0.f);
                if (m < NN) pa[it] = *(const float4*)&g_x[m * IN1 + k0 + 16 + c4 * 4];
                int rb = idx >> 5, cb = idx & 31;
                pb[it] = *(const float4*)&W1[(k0 + 16 + rb) * C1 + bn + cb * 4];
            }
        }
#pragma unroll
        for (int k = 0; k < 16; k++) {
            unsigned long long av[8];
            {
                ulonglong2 t0 = *(const ulonglong2*)&As[k][ty * 16 + 0];
                ulonglong2 t1 = *(const ulonglong2*)&As[k][ty * 16 + 4];
                ulonglong2 t2 = *(const ulonglong2*)&As[k][ty * 16 + 8];
                ulonglong2 t3 = *(const ulonglong2*)&As[k][ty * 16 + 12];
                av[0] = t0.x; av[1] = t0.y; av[2] = t1.x; av[3] = t1.y;
                av[4] = t2.x; av[5] = t2.y; av[6] = t3.x; av[7] = t3.y;
            }
            unsigned long long bv[8];
#pragma unroll
            for (int j = 0; j < 8; j++) bv[j] = Bs2[k][j][tx];
#pragma unroll
            for (int i = 0; i < 8; i++)
#pragma unroll
                for (int j = 0; j < 8; j++)
                    asm("fma.rn.f32x2 %0, %1, %2, %0;"
                        : "+l"(acc2[i][j]) : "l"(av[i]), "l"(bv[j]));
        }
        __syncthreads();
    }

    // ---- epilogue A: fp16 store of h1 ----
#pragma unroll
    for (int i = 0; i < 8; i++) {
        int m0 = bm + ty * 16 + 2 * i;
        if (m0 >= NN) continue;
        __half2 hlo[4], hhi[4];
#pragma unroll
        for (int jj = 0; jj < 4; jj++) {
            float2 a0 = *(float2*)&acc2[i][2 * jj];
            float2 a1 = *(float2*)&acc2[i][2 * jj + 1];
            hlo[jj] = __floats2half2_rn(a0.x, a1.x);
            hhi[jj] = __floats2half2_rn(a0.y, a1.y);
        }
        *(uint4*)&g_h1h[(size_t)m0 * C1 + bn + tx * 8] = *(uint4*)hlo;
        if (m0 + 1 < NN)
            *(uint4*)&g_h1h[(size_t)(m0 + 1) * C1 + bn + tx * 8] = *(uint4*)hhi;
    }

    // ---- epilogue B: attention logits as1/ad1 (from fp32 accumulators) ----
    int head = (bn >> 5) + (tx >> 2);        // global head 0..7
    int coff = (tx & 3) * 8;                 // col offset within head
    unsigned long long ps[8], pd[8];
#pragma unroll
    for (int i = 0; i < 8; i++) { ps[i] = 0ull; pd[i] = 0ull; }
#pragma unroll
    for (int j = 0; j < 8; j++) {
        unsigned long long asv = dup_f32(a_s[head * 32 + coff + j]);
        unsigned long long adv = dup_f32(a_d[head * 32 + coff + j]);
#pragma unroll
        for (int i = 0; i < 8; i++) {
            asm("fma.rn.f32x2 %0, %1, %2, %0;" : "+l"(ps[i]) : "l"(acc2[i][j]), "l"(asv));
            asm("fma.rn.f32x2 %0, %1, %2, %0;" : "+l"(pd[i]) : "l"(acc2[i][j]), "l"(adv));
        }
    }
#pragma unroll
    for (int i = 0; i < 8; i++) {
        float2 vs = *(float2*)&ps[i];
        float2 vd = *(float2*)&pd[i];
        vs.x += __shfl_xor_sync(~0u, vs.x, 1); vs.x += __shfl_xor_sync(~0u, vs.x, 2);
        vs.y += __shfl_xor_sync(~0u, vs.y, 1); vs.y += __shfl_xor_sync(~0u, vs.y, 2);
        vd.x += __shfl_xor_sync(~0u, vd.x, 1); vd.x += __shfl_xor_sync(~0u, vd.x, 2);
        vd.y += __shfl_xor_sync(~0u, vd.y, 1); vd.y += __shfl_xor_sync(~0u, vd.y, 2);
        if ((tx & 3) == 0) {
            int m0 = bm + ty * 16 + 2 * i;
            if (m0 < NN)     { g_as1[m0 * 8 + head] = vs.x; g_ad1[m0 * 8 + head] = vd.x; }
            if (m0 + 1 < NN) { g_as1[(m0 + 1) * 8 + head] = vs.y; g_ad1[(m0 + 1) * 8 + head] = vd.y; }
        }
    }
}

// ---------------- launch 5: scatter edges into CSR + compute softmax numerators ----------------
__global__ void k_scatter_ea(const int* __restrict__ ei) {
    int t = blockIdx.x * blockDim.x + threadIdx.x;
    if (t < EE) {
        int s = ei[t], d = ei[EE + t];
        int p = atomicAdd(&g_cnt[d], 1);
        g_csr[p] = s;
        float4 s0 = *(const float4*)&g_as1[s * 8];
        float4 s1 = *(const float4*)&g_as1[s * 8 + 4];
        float4 d0 = *(const float4*)&g_ad1[d * 8];
        float4 d1 = *(const float4*)&g_ad1[d * 8 + 4];
        float a[8] = {s0.x + d0.x, s0.y + d0.y, s0.z + d0.z, s0.w + d0.w,
                      s1.x + d1.x, s1.y + d1.y, s1.z + d1.z, s1.w + d1.w};
        float e[8];
#pragma unroll
        for (int h = 0; h < 8; h++) {
            float v = a[h] > 0.f ? a[h] : 0.2f * a[h];
            e[h] = __expf(v);
        }
        *(float4*)&g_ea[(size_t)p * 8]     = make_float4(e[0], e[1], e[2], e[3]);
        *(float4*)&g_ea[(size_t)p * 8 + 4] = make_float4(e[4], e[5], e[6], e[7]);
    } else if (t < EE + NN) {
        int i = t - EE;
        int o = g_off[i];
        float4 s0 = *(const float4*)&g_as1[i * 8];
        float4 s1 = *(const float4*)&g_as1[i * 8 + 4];
        float4 d0 = *(const float4*)&g_ad1[i * 8];
        float4 d1 = *(const float4*)&g_ad1[i * 8 + 4];
        float a[8] = {s0.x + d0.x, s0.y + d0.y, s0.z + d0.z, s0.w + d0.w,
                      s1.x + d1.x, s1.y + d1.y, s1.z + d1.z, s1.w + d1.w};
        float e[8];
#pragma unroll
        for (int h = 0; h < 8; h++) {
            float v = a[h] > 0.f ? a[h] : 0.2f * a[h];
            e[h] = __expf(v);
        }
        *(float4*)&g_ea[(size_t)o * 8]     = make_float4(e[0], e[1], e[2], e[3]);
        *(float4*)&g_ea[(size_t)o * 8 + 4] = make_float4(e[4], e[5], e[6], e[7]);
    }
}

// ---------------- launch 6: layer-1 aggregation + elu + fused layer-2 prep ----------------
// warp per dest node; lane covers 8 cols (head = lane>>2). 2-edge software pipeline.
__global__ void __launch_bounds__(256) k_agg1(const float* __restrict__ b1,
                                              const float* __restrict__ W2,
                                              const float* __restrict__ as2,
                                              const float* __restrict__ ad2) {
    int d = (blockIdx.x * blockDim.x + threadIdx.x) >> 5;
    int lane = threadIdx.x & 31;
    if (d >= NN) return;
    int beg = g_off[d], end = g_off[d + 1];
    int myHead = lane >> 2;
    int l7 = lane & 7;

    float acc[8];
#pragma unroll
    for (int j = 0; j < 8; j++) acc[j] = 0.f;
    float z = 0.f;

    for (int base = beg; base < end; base += 32) {
        int cnt = min(32, end - base);
        int sv = (base + lane < end) ? g_csr[base + lane] : 0;
        int j = 0;
        for (; j + 2 <= cnt; j += 2) {
            int s0 = __shfl_sync(~0u, sv, j);
            int s1 = __shfl_sync(~0u, sv, j + 1);
            float v0 = g_ea[(size_t)(base + j) * 8 + l7];
            float v1 = g_ea[(size_t)(base + j + 1) * 8 + l7];
            uint4 h0 = *(const uint4*)&g_h1h[(size_t)s0 * C1 + lane * 8];
            uint4 h1v = *(const uint4*)&g_h1h[(size_t)s1 * C1 + lane * 8];
            if (lane < 8) z += v0 + v1;
            float e0 = __shfl_sync(~0u, v0, myHead);
            float e1 = __shfl_sync(~0u, v1, myHead);
            __half2* p0 = (__half2*)&h0;
            __half2* p1 = (__half2*)&h1v;
#pragma unroll
            for (int q = 0; q < 4; q++) {
                float2 f0 = __half22float2(p0[q]);
                float2 f1 = __half22float2(p1[q]);
                acc[2 * q]     += e0 * f0.x + e1 * f1.x;
                acc[2 * q + 1] += e0 * f0.y + e1 * f1.y;
            }
        }
        if (j < cnt) {
            int s0 = __shfl_sync(~0u, sv, j);
            float v0 = g_ea[(size_t)(base + j) * 8 + l7];
            uint4 h0 = *(const uint4*)&g_h1h[(size_t)s0 * C1 + lane * 8];
            if (lane < 8) z += v0;
            float e0 = __shfl_sync(~0u, v0, myHead);
            __half2* p0 = (__half2*)&h0;
#pragma unroll
            for (int q = 0; q < 4; q++) {
                float2 f0 = __half22float2(p0[q]);
                acc[2 * q]     += e0 * f0.x;
                acc[2 * q + 1] += e0 * f0.y;
            }
        }
    }
    float zh = __shfl_sync(~0u, z, myHead) + 1e-16f;
    float inv = 1.f / zh;

    float x1[8];
    float4 bA = *(const float4*)&b1[lane * 8];
    float4 bB = *(const float4*)&b1[lane * 8 + 4];
    float bb[8] = {bA.x, bA.y, bA.z, bA.w, bB.x, bB.y, bB.z, bB.w};
#pragma unroll
    for (int j = 0; j < 8; j++) {
        float v = acc[j] * inv + bb[j];
        x1[j] = v > 0.f ? v : expm1f(v);
    }

    // fused layer-2: h2 = x1 @ W2
    float p[8];
#pragma unroll
    for (int o = 0; o < 8; o++) p[o] = 0.f;
#pragma unroll
    for (int j = 0; j < 8; j++) {
        int c = lane * 8 + j;
        float4 w0 = *(const float4*)&W2[c * 8];
        float4 w1 = *(const float4*)&W2[c * 8 + 4];
        p[0] += x1[j] * w0.x; p[1] += x1[j] * w0.y;
        p[2] += x1[j] * w0.z; p[3] += x1[j] * w0.w;
        p[4] += x1[j] * w1.x; p[5] += x1[j] * w1.y;
        p[6] += x1[j] * w1.z; p[7] += x1[j] * w1.w;
    }
#pragma unroll
    for (int o = 0; o < 8; o++)
#pragma unroll
        for (int k = 16; k > 0; k >>= 1) p[o] += __shfl_xor_sync(~0u, p[o], k);

    float s2 = 0.f, d2 = 0.f;
#pragma unroll
    for (int o = 0; o < 8; o++) { s2 += p[o] * as2[o]; d2 += p[o] * ad2[o]; }
    if (lane == 0) {
        g_a2s[d] = s2; g_a2d[d] = d2;
        *(float4*)&g_h2[d * 8]     = make_float4(p[0], p[1], p[2], p[3]);
        *(float4*)&g_h2[d * 8 + 4] = make_float4(p[4], p[5], p[6], p[7]);
    }
}

// ---------------- launch 7: layer-2 aggregation + log_softmax ----------------
__global__ void __launch_bounds__(256) k_agg2(const float* __restrict__ b2,
                                              float* __restrict__ out) {
    int d = (blockIdx.x * blockDim.x + threadIdx.x) >> 5;
    int lane = threadIdx.x & 31;
    if (d >= NN) return;
    int beg = g_off[d], end = g_off[d + 1];
    float adv = g_a2d[d];

    float z = 0.f, acc[8];
#pragma unroll
    for (int o = 0; o < 8; o++) acc[o] = 0.f;
    for (int e = beg + lane; e < end; e += 32) {
        int s = g_csr[e];
        float a = g_a2s[s] + adv;
        a = a > 0.f ? a : 0.2f * a;
        float ea = __expf(a);
        z += ea;
        const float4* hp = (const float4*)&g_h2[s * 8];
        float4 v0 = hp[0], v1 = hp[1];
        acc[0] += ea * v0.x; acc[1] += ea * v0.y; acc[2] += ea * v0.z; acc[3] += ea * v0.w;
        acc[4] += ea * v1.x; acc[5] += ea * v1.y; acc[6] += ea * v1.z; acc[7] += ea * v1.w;
    }
#pragma unroll
    for (int k = 16; k > 0; k >>= 1) z += __shfl_xor_sync(~0u, z, k);
#pragma unroll
    for (int o = 0; o < 8; o++)
#pragma unroll
        for (int k = 16; k > 0; k >>= 1) acc[o] += __shfl_xor_sync(~0u, acc[o], k);

    float inv = 1.f / (z + 1e-16f);
    float v[8], mx = -1e30f;
#pragma unroll
    for (int o = 0; o < 8; o++) { v[o] = acc[o] * inv + b2[o]; mx = fmaxf(mx, v[o]); }
    float se = 0.f;
#pragma unroll
    for (int o = 0; o < 8; o++) se += expf(v[o] - mx);
    float lse = mx + logf(se);
    if (lane == 0) {
        *(float4*)&out[d * 8]     = make_float4(v[0] - lse, v[1] - lse, v[2] - lse, v[3] - lse);
        *(float4*)&out[d * 8 + 4] = make_float4(v[4] - lse, v[5] - lse, v[6] - lse, v[7] - lse);
    }
}

// ---------------- launch ----------------
extern "C" void kernel_launch(void* const* d_in, const int* in_sizes, int n_in,
                              void* d_out, int out_size) {
    const float* high  = (const float*)d_in[0];
    const float* low   = (const float*)d_in[1];
    const int*   ei    = (const int*)d_in[2];
    const float* Wemb  = (const float*)d_in[3];
    const float* bemb  = (const float*)d_in[4];
    const float* W1    = (const float*)d_in[5];
    const float* asrc1 = (const float*)d_in[6];
    const float* adst1 = (const float*)d_in[7];
    const float* b1    = (const float*)d_in[8];
    const float* W2    = (const float*)d_in[9];
    const float* as2   = (const float*)d_in[10];
    const float* ad2   = (const float*)d_in[11];
    const float* b2    = (const float*)d_in[12];
    float* out = (float*)d_out;

    dim3 eb(192, 2);
    k_emb<<<NN / 2, eb>>>(high, low, Wemb, bemb);               // 1
    k_cnt_edges<<<(EE + 255) / 256, 256>>>(ei);                 // 2
    k_scan<<<1, 1024>>>();                                      // 3

    dim3 gg((NN + 127) / 128, C1 / 128);
    k_gemm<<<gg, 128>>>(W1, asrc1, adst1);                      // 4  <- ncu lands here

    k_scatter_ea<<<(EE + NN + 255) / 256, 256>>>(ei);           // 5
    k_agg1<<<(NN + 7) / 8, 256>>>(b1, W2, as2, ad2);            // 6
    k_agg2<<<(NN + 7) / 8, 256>>>(b2, out);                     // 7
}

// round 6
// speedup vs baseline: 1.3812x; 1.3812x over previous
#include <cuda_runtime.h>
#include <cuda_fp16.h>

#define NN   50000
#define EE   800000
#define EPAD 850000
#define IN1  192
#define C1   256

// ---------------- scratch (device globals; zero-initialized at load) ----------------
__device__ __half g_xh [NN * IN1];      // fp16 concat(high, elu(emb))
__device__ __half g_w1t[C1 * IN1];      // W1 transposed [n][k] fp16
__device__ __half g_h1h[(size_t)NN * C1];
__device__ float  g_E1s[NN * 8];        // exp(as1)
__device__ float  g_E2s[NN * 8];        // exp(0.2*as1)
__device__ float  g_E1d[NN * 8];        // exp(ad1)
__device__ float  g_E2d[NN * 8];        // exp(0.2*ad1)
__device__ float  g_h2 [NN * 8];
__device__ float  g_p1 [NN];            // exp(a2s)
__device__ float  g_p2 [NN];            // exp(0.2*a2s)
__device__ float  g_q1 [NN];            // exp(a2d)
__device__ float  g_q2 [NN];            // exp(0.2*a2d)
__device__ int    g_cnt[NN];            // degree counts -> cursor; re-zeroed by agg1
__device__ int2   g_seg[NN];            // (beg, end) per destination
__device__ int    g_csr[EPAD];

#define EMB_B  25000
#define EDGE_B ((EE + 383) / 384)
#define W1T_B  ((C1 * IN1 + 383) / 384)

// ---------------- launch 1: emb+concat (fp16), degree count, W1 transpose ----------------
__global__ void k_front(const float* __restrict__ high, const float* __restrict__ low,
                        const float* __restrict__ Wemb, const float* __restrict__ bemb,
                        const float* __restrict__ W1, const int* __restrict__ ei) {
    int bid = blockIdx.x;
    int tid = threadIdx.y * 192 + threadIdx.x;
    if (bid < EMB_B) {
        __shared__ float ls[2][32];
        int n = bid * 2 + threadIdx.y;
        int c = threadIdx.x;
        if (c < 32) ls[threadIdx.y][c] = low[n * 32 + c];
        __syncthreads();
        if (c < 128) {
            g_xh[n * IN1 + c] = __float2half(high[n * 128 + c]);
        } else {
            int j = c - 128;
            float s = bemb[j];
#pragma unroll
            for (int k = 0; k < 32; k++) s += ls[threadIdx.y][k] * Wemb[k * 64 + j];
            s = s > 0.f ? s : expm1f(s);
            g_xh[n * IN1 + c] = __float2half(s);
        }
    } else if (bid < EMB_B + EDGE_B) {
        int e = (bid - EMB_B) * 384 + tid;
        if (e < EE) atomicAdd(&g_cnt[ei[EE + e]], 1);
    } else {
        int j = (bid - EMB_B - EDGE_B) * 384 + tid;
        if (j < C1 * IN1) {
            int k = j >> 8, n = j & 255;
            g_w1t[n * IN1 + k] = __float2half(W1[j]);
        }
    }
}

// ---------------- launch 2: segment assignment (two-pass, low-register scan) ----------------
__global__ void __launch_bounds__(1024) k_scan() {
    int t = threadIdx.x;
    int s = 0;
    for (int i = 0; i < 49; i++) {
        int idx = t + i * 1024;
        if (idx < NN) s += g_cnt[idx] + 1;   // +1 self loop
    }
    int lane = t & 31, wid = t >> 5;
    int v = s;
#pragma unroll
    for (int o = 1; o < 32; o <<= 1) {
        int u = __shfl_up_sync(~0u, v, o);
        if (lane >= o) v += u;
    }
    __shared__ int wsum[32];
    if (lane == 31) wsum[wid] = v;
    __syncthreads();
    if (wid == 0) {
        int w = wsum[lane];
#pragma unroll
        for (int o = 1; o < 32; o <<= 1) {
            int u = __shfl_up_sync(~0u, w, o);
            if (lane >= o) w += u;
        }
        wsum[lane] = w;
    }
    __syncthreads();
    int base = v - s + (wid ? wsum[wid - 1] : 0);
    for (int i = 0; i < 49; i++) {
        int idx = t + i * 1024;
        if (idx < NN) {
            int cnt = g_cnt[idx] + 1;
            g_seg[idx] = make_int2(base, base + cnt);
            g_csr[base] = idx;            // self loop in slot 0
            g_cnt[idx] = base + 1;        // scatter cursor
            base += cnt;
        }
    }
}

// ---------------- launch 3: edge scatter into CSR ----------------
__global__ void k_scatter(const int* __restrict__ ei) {
    int e = blockIdx.x * blockDim.x + threadIdx.x;
    if (e < EE) {
        int s = ei[e], d = ei[EE + e];
        int p = atomicAdd(&g_cnt[d], 1);
        g_csr[p] = s;
    }
}

// ---------------- launch 4 (ncu target): fp16 tensor-core GEMM + attention epilogue ----------------
__device__ __forceinline__ void ldsm4(unsigned& r0, unsigned& r1, unsigned& r2, unsigned& r3,
                                      unsigned addr) {
    asm volatile("ldmatrix.sync.aligned.m8n8.x4.shared.b16 {%0,%1,%2,%3},[%4];"
                 : "=r"(r0), "=r"(r1), "=r"(r2), "=r"(r3) : "r"(addr));
}
__device__ __forceinline__ void mma16816(float& c0, float& c1, float& c2, float& c3,
                                         unsigned a0, unsigned a1, unsigned a2, unsigned a3,
                                         unsigned b0, unsigned b1) {
    asm volatile("mma.sync.aligned.m16n8k16.row.col.f32.f16.f16.f32 "
                 "{%0,%1,%2,%3},{%4,%5,%6,%7},{%8,%9},{%0,%1,%2,%3};"
                 : "+f"(c0), "+f"(c1), "+f"(c2), "+f"(c3)
                 : "r"(a0), "r"(a1), "r"(a2), "r"(a3), "r"(b0), "r"(b1));
}

#define RSTR 200   // smem row stride in halfs (400B: conflict-free ldmatrix phases)

__global__ void __launch_bounds__(256) k_gemm(const float* __restrict__ a_s,
                                              const float* __restrict__ a_d) {
    extern __shared__ __half sm[];
    __half* As = sm;                 // 128 x 192 (stride 200)
    __half* Bs = sm + 128 * RSTR;    // 128 x 192 (stride 200)
    int bm = blockIdx.x * 128, bn = blockIdx.y * 128;
    int tid = threadIdx.x, lane = tid & 31, wid = tid >> 5;
    int warpM = wid & 1, warpN = wid >> 1;

    for (int i = tid; i < 128 * 24; i += 256) {
        int r = i / 24, ch = i % 24;
        int m = bm + r;
        uint4 v = make_uint4(0, 0, 0, 0);
        if (m < NN) v = *(const uint4*)&g_xh[m * IN1 + ch * 8];
        *(uint4*)&As[r * RSTR + ch * 8] = v;
    }
    for (int i = tid; i < 128 * 24; i += 256) {
        int r = i / 24, ch = i % 24;
        uint4 v = *(const uint4*)&g_w1t[(bn + r) * IN1 + ch * 8];
        *(uint4*)&Bs[r * RSTR + ch * 8] = v;
    }
    __syncthreads();

    float acc[4][4][4];
#pragma unroll
    for (int i = 0; i < 4; i++)
#pragma unroll
        for (int j = 0; j < 4; j++)
#pragma unroll
            for (int q = 0; q < 4; q++) acc[i][j][q] = 0.f;

    unsigned aB = (unsigned)__cvta_generic_to_shared(As);
    unsigned bB = (unsigned)__cvta_generic_to_shared(Bs);
    unsigned aRow = (unsigned)(warpM * 64 + (lane & 7) + ((lane >> 3) & 1) * 8);
    unsigned aAddr0 = aB + aRow * (RSTR * 2) + (lane >> 4) * 16;
    unsigned bRow = (unsigned)(warpN * 32 + (lane & 7) + (lane >> 4) * 8);
    unsigned bAddr0 = bB + bRow * (RSTR * 2) + ((lane >> 3) & 1) * 16;

#pragma unroll
    for (int kk = 0; kk < 12; kk++) {
        unsigned koff = kk * 32;
        unsigned a[4][4], b[2][4];
#pragma unroll
        for (int mt = 0; mt < 4; mt++)
            ldsm4(a[mt][0], a[mt][1], a[mt][2], a[mt][3],
                  aAddr0 + mt * 16 * (RSTR * 2) + koff);
#pragma unroll
        for (int nh = 0; nh < 2; nh++)
            ldsm4(b[nh][0], b[nh][1], b[nh][2], b[nh][3],
                  bAddr0 + nh * 16 * (RSTR * 2) + koff);
#pragma unroll
        for (int mt = 0; mt < 4; mt++)
#pragma unroll
            for (int nt = 0; nt < 4; nt++)
                mma16816(acc[mt][nt][0], acc[mt][nt][1], acc[mt][nt][2], acc[mt][nt][3],
                         a[mt][0], a[mt][1], a[mt][2], a[mt][3],
                         b[nt >> 1][(nt & 1) * 2], b[nt >> 1][(nt & 1) * 2 + 1]);
    }

    // epilogue A: h1 fp16 stores
    int colBase = bn + warpN * 32;
#pragma unroll
    for (int mt = 0; mt < 4; mt++) {
        int row0 = bm + warpM * 64 + mt * 16 + (lane >> 2);
        int row1 = row0 + 8;
#pragma unroll
        for (int nt = 0; nt < 4; nt++) {
            int col = colBase + nt * 8 + (lane & 3) * 2;
            if (row0 < NN)
                *(__half2*)&g_h1h[(size_t)row0 * C1 + col] =
                    __floats2half2_rn(acc[mt][nt][0], acc[mt][nt][1]);
            if (row1 < NN)
                *(__half2*)&g_h1h[(size_t)row1 * C1 + col] =
                    __floats2half2_rn(acc[mt][nt][2], acc[mt][nt][3]);
        }
    }

    // epilogue B: attention logits -> exp factors (head = this warp's 32 cols)
    int head = (bn >> 5) + warpN;
    float2 asv[4], adv[4];
#pragma unroll
    for (int nt = 0; nt < 4; nt++) {
        asv[nt] = *(const float2*)&a_s[head * 32 + nt * 8 + (lane & 3) * 2];
        adv[nt] = *(const float2*)&a_d[head * 32 + nt * 8 + (lane & 3) * 2];
    }
#pragma unroll
    for (int mt = 0; mt < 4; mt++) {
        float ps0 = 0.f, ps1 = 0.f, pd0 = 0.f, pd1 = 0.f;
#pragma unroll
        for (int nt = 0; nt < 4; nt++) {
            ps0 += acc[mt][nt][0] * asv[nt].x + acc[mt][nt][1] * asv[nt].y;
            ps1 += acc[mt][nt][2] * asv[nt].x + acc[mt][nt][3] * asv[nt].y;
            pd0 += acc[mt][nt][0] * adv[nt].x + acc[mt][nt][1] * adv[nt].y;
            pd1 += acc[mt][nt][2] * adv[nt].x + acc[mt][nt][3] * adv[nt].y;
        }
#pragma unroll
        for (int o = 1; o < 4; o <<= 1) {
            ps0 += __shfl_xor_sync(~0u, ps0, o);
            ps1 += __shfl_xor_sync(~0u, ps1, o);
            pd0 += __shfl_xor_sync(~0u, pd0, o);
            pd1 += __shfl_xor_sync(~0u, pd1, o);
        }
        if ((lane & 3) == 0) {
            int row0 = bm + warpM * 64 + mt * 16 + (lane >> 2);
            int row1 = row0 + 8;
            if (row0 < NN) {
                g_E1s[row0 * 8 + head] = __expf(ps0);
                g_E2s[row0 * 8 + head] = __expf(0.2f * ps0);
                g_E1d[row0 * 8 + head] = __expf(pd0);
                g_E2d[row0 * 8 + head] = __expf(0.2f * pd0);
            }
            if (row1 < NN) {
                g_E1s[row1 * 8 + head] = __expf(ps1);
                g_E2s[row1 * 8 + head] = __expf(0.2f * ps1);
                g_E1d[row1 * 8 + head] = __expf(pd1);
                g_E2d[row1 * 8 + head] = __expf(0.2f * pd1);
            }
        }
    }
}

// ---------------- launch 5: layer-1 aggregation + elu + fused layer-2 prep ----------------
__global__ void __launch_bounds__(256) k_agg1(const float* __restrict__ b1,
                                              const float* __restrict__ W2,
                                              const float* __restrict__ as2,
                                              const float* __restrict__ ad2) {
    int d = (blockIdx.x * blockDim.x + threadIdx.x) >> 5;
    int lane = threadIdx.x & 31;
    if (d >= NN) return;
    int2 seg = g_seg[d];
    int beg = seg.x, end = seg.y;
    int h = lane & 7;
    int myHead = lane >> 2;

    float E1d = g_E1d[d * 8 + h];
    float E2d = g_E2d[d * 8 + h];

    float acc[8];
#pragma unroll
    for (int j = 0; j < 8; j++) acc[j] = 0.f;
    float z = 0.f;

    for (int base = beg; base < end; base += 32) {
        int cnt = min(32, end - base);
        int sv = g_csr[min(base + lane, end - 1)];
        for (int g0 = 0; g0 < cnt; g0 += 4) {
            int eI = g0 + (lane >> 3);
            int se = __shfl_sync(~0u, sv, min(eI, cnt - 1));
            float ea = 0.f;
            if (eI < cnt) {
                float e1 = g_E1s[se * 8 + h];
                float e2 = g_E2s[se * 8 + h];
                ea = fmaxf(e1 * E1d, e2 * E2d);
            }
            z += ea;
            int lim = min(4, cnt - g0);
            for (int j = 0; j < lim; j++) {
                int s = __shfl_sync(~0u, sv, g0 + j);
                float eh = __shfl_sync(~0u, ea, j * 8 + myHead);
                uint4 hv = *(const uint4*)&g_h1h[(size_t)s * C1 + lane * 8];
                __half2* hp = (__half2*)&hv;
#pragma unroll
                for (int q = 0; q < 4; q++) {
                    float2 f = __half22float2(hp[q]);
                    acc[2 * q]     += eh * f.x;
                    acc[2 * q + 1] += eh * f.y;
                }
            }
        }
    }
    z += __shfl_xor_sync(~0u, z, 8);
    z += __shfl_xor_sync(~0u, z, 16);
    float zh = __shfl_sync(~0u, z, myHead);
    float inv = 1.f / (zh + 1e-16f);

    float x1[8];
    float4 bA = *(const float4*)&b1[lane * 8];
    float4 bB = *(const float4*)&b1[lane * 8 + 4];
    float bb[8] = {bA.x, bA.y, bA.z, bA.w, bB.x, bB.y, bB.z, bB.w};
#pragma unroll
    for (int j = 0; j < 8; j++) {
        float v = acc[j] * inv + bb[j];
        x1[j] = v > 0.f ? v : expm1f(v);
    }

    float p[8];
#pragma unroll
    for (int o = 0; o < 8; o++) p[o] = 0.f;
#pragma unroll
    for (int j = 0; j < 8; j++) {
        int c = lane * 8 + j;
        float4 w0 = *(const float4*)&W2[c * 8];
        float4 w1 = *(const float4*)&W2[c * 8 + 4];
        p[0] += x1[j] * w0.x; p[1] += x1[j] * w0.y;
        p[2] += x1[j] * w0.z; p[3] += x1[j] * w0.w;
        p[4] += x1[j] * w1.x; p[5] += x1[j] * w1.y;
        p[6] += x1[j] * w1.z; p[7] += x1[j] * w1.w;
    }
#pragma unroll
    for (int o = 0; o < 8; o++)
#pragma unroll
        for (int k = 16; k > 0; k >>= 1) p[o] += __shfl_xor_sync(~0u, p[o], k);

    float s2 = 0.f, d2 = 0.f;
#pragma unroll
    for (int o = 0; o < 8; o++) { s2 += p[o] * as2[o]; d2 += p[o] * ad2[o]; }
    if (lane == 0) {
        g_p1[d] = __expf(s2);
        g_p2[d] = __expf(0.2f * s2);
        g_q1[d] = __expf(d2);
        g_q2[d] = __expf(0.2f * d2);
        *(float4*)&g_h2[d * 8]     = make_float4(p[0], p[1], p[2], p[3]);
        *(float4*)&g_h2[d * 8 + 4] = make_float4(p[4], p[5], p[6], p[7]);
        g_cnt[d] = 0;   // reset for next replay
    }
}

// ---------------- launch 6: layer-2 aggregation + log_softmax ----------------
__global__ void __launch_bounds__(256) k_agg2(const float* __restrict__ b2,
                                              float* __restrict__ out) {
    int d = (blockIdx.x * blockDim.x + threadIdx.x) >> 5;
    int lane = threadIdx.x & 31;
    if (d >= NN) return;
    int2 seg = g_seg[d];
    int beg = seg.x, end = seg.y;
    float q1 = g_q1[d], q2 = g_q2[d];

    float z = 0.f, acc[8];
#pragma unroll
    for (int o = 0; o < 8; o++) acc[o] = 0.f;
    for (int e = beg + lane; e < end; e += 32) {
        int s = g_csr[e];
        float ea = fmaxf(g_p1[s] * q1, g_p2[s] * q2);
        z += ea;
        const float4* hp = (const float4*)&g_h2[s * 8];
        float4 v0 = hp[0], v1 = hp[1];
        acc[0] += ea * v0.x; acc[1] += ea * v0.y; acc[2] += ea * v0.z; acc[3] += ea * v0.w;
        acc[4] += ea * v1.x; acc[5] += ea * v1.y; acc[6] += ea * v1.z; acc[7] += ea * v1.w;
    }
#pragma unroll
    for (int k = 16; k > 0; k >>= 1) z += __shfl_xor_sync(~0u, z, k);
#pragma unroll
    for (int o = 0; o < 8; o++)
#pragma unroll
        for (int k = 16; k > 0; k >>= 1) acc[o] += __shfl_xor_sync(~0u, acc[o], k);

    float inv = 1.f / (z + 1e-16f);
    float v[8], mx = -1e30f;
#pragma unroll
    for (int o = 0; o < 8; o++) { v[o] = acc[o] * inv + b2[o]; mx = fmaxf(mx, v[o]); }
    float se = 0.f;
#pragma unroll
    for (int o = 0; o < 8; o++) se += expf(v[o] - mx);
    float lse = mx + logf(se);
    if (lane == 0) {
        *(float4*)&out[d * 8]     = make_float4(v[0] - lse, v[1] - lse, v[2] - lse, v[3] - lse);
        *(float4*)&out[d * 8 + 4] = make_float4(v[4] - lse, v[5] - lse, v[6] - lse, v[7] - lse);
    }
}

// ---------------- launch ----------------
extern "C" void kernel_launch(void* const* d_in, const int* in_sizes, int n_in,
                              void* d_out, int out_size) {
    const float* high  = (const float*)d_in[0];
    const float* low   = (const float*)d_in[1];
    const int*   ei    = (const int*)d_in[2];
    const float* Wemb  = (const float*)d_in[3];
    const float* bemb  = (const float*)d_in[4];
    const float* W1    = (const float*)d_in[5];
    const float* asrc1 = (const float*)d_in[6];
    const float* adst1 = (const float*)d_in[7];
    const float* b1    = (const float*)d_in[8];
    const float* W2    = (const float*)d_in[9];
    const float* as2   = (const float*)d_in[10];
    const float* ad2   = (const float*)d_in[11];
    const float* b2    = (const float*)d_in[12];
    float* out = (float*)d_out;

    cudaFuncSetAttribute(k_gemm, cudaFuncAttributeMaxDynamicSharedMemorySize,
                         2 * 128 * RSTR * (int)sizeof(__half));

    dim3 fb(192, 2);
    k_front<<<EMB_B + EDGE_B + W1T_B, fb>>>(high, low, Wemb, bemb, W1, ei);   // 1
    k_scan<<<1, 1024>>>();                                                    // 2
    k_scatter<<<(EE + 255) / 256, 256>>>(ei);                                 // 3
    dim3 gg((NN + 127) / 128, 2);
    k_gemm<<<gg, 256, 2 * 128 * RSTR * (int)sizeof(__half)>>>(asrc1, adst1);  // 4 <- ncu
    k_agg1<<<(NN + 7) / 8, 256>>>(b1, W2, as2, ad2);                          // 5
    k_agg2<<<(NN + 7) / 8, 256>>>(b2, out);                                   // 6
}

// round 13
// speedup vs baseline: 1.4965x; 1.0835x over previous
#include <cuda_runtime.h>
#include <cuda_fp16.h>

#define NN   50000
#define EE   800000
#define EPAD 850000
#define IN1  192
#define C1   256

// ---------------- scratch (device globals; zero-initialized at load) ----------------
__device__ __half g_xh [NN * IN1];
__device__ __half g_w1t[C1 * IN1];
__device__ __half g_h1h[(size_t)NN * C1];
__device__ float2 g_Es [NN * 8];        // {exp(as1), exp(0.2*as1)}
__device__ float2 g_Ed [NN * 8];        // {exp(ad1), exp(0.2*ad1)}
__device__ float  g_h2 [NN * 8];
__device__ float2 g_P  [NN];            // {exp(a2s), exp(0.2*a2s)}
__device__ float2 g_Q  [NN];            // {exp(a2d), exp(0.2*a2d)}
__device__ int    g_cnt[NN];
__device__ int2   g_seg[NN];
__device__ int    g_csr[EPAD];

#define EMB_B  25000
#define EDGE_B ((EE + 383) / 384)
#define W1T_B  ((C1 * IN1 + 383) / 384)

// ---------------- launch 1: emb+concat (fp16), degree count, W1 transpose ----------------
__global__ void k_front(const float* __restrict__ high, const float* __restrict__ low,
                        const float* __restrict__ Wemb, const float* __restrict__ bemb,
                        const float* __restrict__ W1, const int* __restrict__ ei) {
    int bid = blockIdx.x;
    int tid = threadIdx.y * 192 + threadIdx.x;
    if (bid < EMB_B) {
        __shared__ float ls[2][32];
        int n = bid * 2 + threadIdx.y;
        int c = threadIdx.x;
        if (c < 32) ls[threadIdx.y][c] = low[n * 32 + c];
        __syncthreads();
        if (c < 128) {
            g_xh[n * IN1 + c] = __float2half(high[n * 128 + c]);
        } else {
            int j = c - 128;
            float s = bemb[j];
#pragma unroll
            for (int k = 0; k < 32; k++) s += ls[threadIdx.y][k] * Wemb[k * 64 + j];
            s = s > 0.f ? s : expm1f(s);
            g_xh[n * IN1 + c] = __float2half(s);
        }
    } else if (bid < EMB_B + EDGE_B) {
        int e = (bid - EMB_B) * 384 + tid;
        if (e < EE) atomicAdd(&g_cnt[ei[EE + e]], 1);
    } else {
        int j = (bid - EMB_B - EDGE_B) * 384 + tid;
        if (j < C1 * IN1) {
            int k = j >> 8, n = j & 255;
            g_w1t[n * IN1 + k] = __float2half(W1[j]);
        }
    }
}

// ---------------- launch 2: segment assignment scan ----------------
__global__ void __launch_bounds__(1024) k_scan() {
    int t = threadIdx.x;
    int s = 0;
    for (int i = 0; i < 49; i++) {
        int idx = t + i * 1024;
        if (idx < NN) s += g_cnt[idx] + 1;
    }
    int lane = t & 31, wid = t >> 5;
    int v = s;
#pragma unroll
    for (int o = 1; o < 32; o <<= 1) {
        int u = __shfl_up_sync(~0u, v, o);
        if (lane >= o) v += u;
    }
    __shared__ int wsum[32];
    if (lane == 31) wsum[wid] = v;
    __syncthreads();
    if (wid == 0) {
        int w = wsum[lane];
#pragma unroll
        for (int o = 1; o < 32; o <<= 1) {
            int u = __shfl_up_sync(~0u, w, o);
            if (lane >= o) w += u;
        }
        wsum[lane] = w;
    }
    __syncthreads();
    int base = v - s + (wid ? wsum[wid - 1] : 0);
    for (int i = 0; i < 49; i++) {
        int idx = t + i * 1024;
        if (idx < NN) {
            int cnt = g_cnt[idx] + 1;
            g_seg[idx] = make_int2(base, base + cnt);
            g_csr[base] = idx;
            g_cnt[idx] = base + 1;
            base += cnt;
        }
    }
}

// ---------------- launch 3: edge scatter into CSR ----------------
__global__ void k_scatter(const int* __restrict__ ei) {
    int e = blockIdx.x * blockDim.x + threadIdx.x;
    if (e < EE) {
        int s = ei[e], d = ei[EE + e];
        int p = atomicAdd(&g_cnt[d], 1);
        g_csr[p] = s;
    }
}

// ---------------- launch 4 (ncu target): pipelined fp16 HMMA GEMM + attention epilogue ----------------
__device__ __forceinline__ void ldsm4(unsigned& r0, unsigned& r1, unsigned& r2, unsigned& r3,
                                      unsigned addr) {
    asm volatile("ldmatrix.sync.aligned.m8n8.x4.shared.b16 {%0,%1,%2,%3},[%4];"
                 : "=r"(r0), "=r"(r1), "=r"(r2), "=r"(r3) : "r"(addr));
}
__device__ __forceinline__ void mma16816(float& c0, float& c1, float& c2, float& c3,
                                         unsigned a0, unsigned a1, unsigned a2, unsigned a3,
                                         unsigned b0, unsigned b1) {
    asm volatile("mma.sync.aligned.m16n8k16.row.col.f32.f16.f16.f32 "
                 "{%0,%1,%2,%3},{%4,%5,%6,%7},{%8,%9},{%0,%1,%2,%3};"
                 : "+f"(c0), "+f"(c1), "+f"(c2), "+f"(c3)
                 : "r"(a0), "r"(a1), "r"(a2), "r"(a3), "r"(b0), "r"(b1));
}
__device__ __forceinline__ void cpasync16(unsigned dst, const void* src, int sz) {
    asm volatile("cp.async.ca.shared.global [%0], [%1], 16, %2;"
                 :: "r"(dst), "l"(src), "r"(sz));
}

#define RS       72                    // smem row stride (halfs) — conflict-free ldmatrix
#define MAT_B    (128 * RS * 2)        // bytes per 128x64 matrix stage (18432)
#define STAGE_B  (2 * MAT_B)           // A + B per stage (36864)
#define SMEM_B   (3 * STAGE_B)         // 110592

__global__ void __launch_bounds__(256) k_gemm(const float* __restrict__ a_s,
                                              const float* __restrict__ a_d) {
    extern __shared__ __half sm[];
    unsigned smBase = (unsigned)__cvta_generic_to_shared(sm);
    int bm = blockIdx.x * 128, bn = blockIdx.y * 128;
    int tid = threadIdx.x, lane = tid & 31, wid = tid >> 5;
    int warpM = wid & 1, warpN = wid >> 1;

    // issue all 3 K-chunk loads up-front (one cp.async group per chunk)
    // each chunk: 128 rows x 64 halfs = 1024 x 16B transfers per matrix
#pragma unroll
    for (int c = 0; c < 3; c++) {
        unsigned aS = smBase + c * STAGE_B;
        unsigned bS = aS + MAT_B;
#pragma unroll
        for (int i = tid; i < 1024; i += 256) {
            int r = i >> 3, ch = i & 7;
            int m = bm + r;
            const __half* src = &g_xh[(size_t)min(m, NN - 1) * IN1 + c * 64 + ch * 8];
            cpasync16(aS + (r * RS + ch * 8) * 2, src, m < NN ? 16 : 0);
        }
#pragma unroll
        for (int i = tid; i < 1024; i += 256) {
            int r = i >> 3, ch = i & 7;
            cpasync16(bS + (r * RS + ch * 8) * 2, &g_w1t[(bn + r) * IN1 + c * 64 + ch * 8], 16);
        }
        asm volatile("cp.async.commit_group;" ::: "memory");
    }

    float acc[4][4][4];
#pragma unroll
    for (int i = 0; i < 4; i++)
#pragma unroll
        for (int j = 0; j < 4; j++)
#pragma unroll
            for (int q = 0; q < 4; q++) acc[i][j][q] = 0.f;

    unsigned aRow = (unsigned)(warpM * 64 + (lane & 7) + ((lane >> 3) & 1) * 8);
    unsigned bRow = (unsigned)(warpN * 32 + (lane & 7) + (lane >> 4) * 8);

    for (int c = 0; c < 3; c++) {
        if (c == 0)      asm volatile("cp.async.wait_group 2;" ::: "memory");
        else if (c == 1) asm volatile("cp.async.wait_group 1;" ::: "memory");
        else             asm volatile("cp.async.wait_group 0;" ::: "memory");
        __syncthreads();
        unsigned aB = smBase + c * STAGE_B;
        unsigned bB = aB + MAT_B;
        unsigned aAddr0 = aB + aRow * (RS * 2) + (lane >> 4) * 16;
        unsigned bAddr0 = bB + bRow * (RS * 2) + ((lane >> 3) & 1) * 16;
#pragma unroll
        for (int kk = 0; kk < 4; kk++) {
            unsigned koff = kk * 32;
            unsigned a[4][4], b[2][4];
#pragma unroll
            for (int mt = 0; mt < 4; mt++)
                ldsm4(a[mt][0], a[mt][1], a[mt][2], a[mt][3],
                      aAddr0 + mt * 16 * (RS * 2) + koff);
#pragma unroll
            for (int nh = 0; nh < 2; nh++)
                ldsm4(b[nh][0], b[nh][1], b[nh][2], b[nh][3],
                      bAddr0 + nh * 16 * (RS * 2) + koff);
#pragma unroll
            for (int mt = 0; mt < 4; mt++)
#pragma unroll
                for (int nt = 0; nt < 4; nt++)
                    mma16816(acc[mt][nt][0], acc[mt][nt][1], acc[mt][nt][2], acc[mt][nt][3],
                             a[mt][0], a[mt][1], a[mt][2], a[mt][3],
                             b[nt >> 1][(nt & 1) * 2], b[nt >> 1][(nt & 1) * 2 + 1]);
        }
    }

    // epilogue A: h1 fp16 stores
    int colBase = bn + warpN * 32;
#pragma unroll
    for (int mt = 0; mt < 4; mt++) {
        int row0 = bm + warpM * 64 + mt * 16 + (lane >> 2);
        int row1 = row0 + 8;
#pragma unroll
        for (int nt = 0; nt < 4; nt++) {
            int col = colBase + nt * 8 + (lane & 3) * 2;
            if (row0 < NN)
                *(__half2*)&g_h1h[(size_t)row0 * C1 + col] =
                    __floats2half2_rn(acc[mt][nt][0], acc[mt][nt][1]);
            if (row1 < NN)
                *(__half2*)&g_h1h[(size_t)row1 * C1 + col] =
                    __floats2half2_rn(acc[mt][nt][2], acc[mt][nt][3]);
        }
    }

    // epilogue B: attention logits -> interleaved exp factors
    int head = (bn >> 5) + warpN;
    float2 asv[4], adv[4];
#pragma unroll
    for (int nt = 0; nt < 4; nt++) {
        asv[nt] = *(const float2*)&a_s[head * 32 + nt * 8 + (lane & 3) * 2];
        adv[nt] = *(const float2*)&a_d[head * 32 + nt * 8 + (lane & 3) * 2];
    }
#pragma unroll
    for (int mt = 0; mt < 4; mt++) {
        float ps0 = 0.f, ps1 = 0.f, pd0 = 0.f, pd1 = 0.f;
#pragma unroll
        for (int nt = 0; nt < 4; nt++) {
            ps0 += acc[mt][nt][0] * asv[nt].x + acc[mt][nt][1] * asv[nt].y;
            ps1 += acc[mt][nt][2] * asv[nt].x + acc[mt][nt][3] * asv[nt].y;
            pd0 += acc[mt][nt][0] * adv[nt].x + acc[mt][nt][1] * adv[nt].y;
            pd1 += acc[mt][nt][2] * adv[nt].x + acc[mt][nt][3] * adv[nt].y;
        }
#pragma unroll
        for (int o = 1; o < 4; o <<= 1) {
            ps0 += __shfl_xor_sync(~0u, ps0, o);
            ps1 += __shfl_xor_sync(~0u, ps1, o);
            pd0 += __shfl_xor_sync(~0u, pd0, o);
            pd1 += __shfl_xor_sync(~0u, pd1, o);
        }
        if ((lane & 3) == 0) {
            int row0 = bm + warpM * 64 + mt * 16 + (lane >> 2);
            int row1 = row0 + 8;
            if (row0 < NN) {
                g_Es[row0 * 8 + head] = make_float2(__expf(ps0), __expf(0.2f * ps0));
                g_Ed[row0 * 8 + head] = make_float2(__expf(pd0), __expf(0.2f * pd0));
            }
            if (row1 < NN) {
                g_Es[row1 * 8 + head] = make_float2(__expf(ps1), __expf(0.2f * ps1));
                g_Ed[row1 * 8 + head] = make_float2(__expf(pd1), __expf(0.2f * pd1));
            }
        }
    }
}

// ---------------- launch 5: layer-1 aggregation (per-lane ea, no cross-lane deps) ----------------
__global__ void __launch_bounds__(256) k_agg1(const float* __restrict__ b1,
                                              const float* __restrict__ W2,
                                              const float* __restrict__ as2,
                                              const float* __restrict__ ad2) {
    int d = (blockIdx.x * blockDim.x + threadIdx.x) >> 5;
    int lane = threadIdx.x & 31;
    if (d >= NN) return;
    int2 seg = g_seg[d];
    int beg = seg.x, end = seg.y;
    int h = lane >> 2;                         // head owning cols lane*8..+7
    float2 Ed = g_Ed[d * 8 + h];

    float acc[8];
#pragma unroll
    for (int j = 0; j < 8; j++) acc[j] = 0.f;
    float z = 0.f;

    for (int base = beg; base < end; base += 32) {
        int cnt = min(32, end - base);
        int sv = g_csr[min(base + lane, end - 1)];
        int j = 0;
        for (; j + 2 <= cnt; j += 2) {
            int s0 = __shfl_sync(~0u, sv, j);
            int s1 = __shfl_sync(~0u, sv, j + 1);
            float2 E0 = g_Es[s0 * 8 + h];
            float2 E1 = g_Es[s1 * 8 + h];
            uint4 hv0 = *(const uint4*)&g_h1h[(size_t)s0 * C1 + lane * 8];
            uint4 hv1 = *(const uint4*)&g_h1h[(size_t)s1 * C1 + lane * 8];
            float ea0 = fmaxf(E0.x * Ed.x, E0.y * Ed.y);
            float ea1 = fmaxf(E1.x * Ed.x, E1.y * Ed.y);
            z += ea0 + ea1;
            __half2* p0 = (__half2*)&hv0;
            __half2* p1 = (__half2*)&hv1;
#pragma unroll
            for (int q = 0; q < 4; q++) {
                float2 f0 = __half22float2(p0[q]);
                float2 f1 = __half22float2(p1[q]);
                acc[2 * q]     += ea0 * f0.x + ea1 * f1.x;
                acc[2 * q + 1] += ea0 * f0.y + ea1 * f1.y;
            }
        }
        if (j < cnt) {
            int s0 = __shfl_sync(~0u, sv, j);
            float2 E0 = g_Es[s0 * 8 + h];
            uint4 hv0 = *(const uint4*)&g_h1h[(size_t)s0 * C1 + lane * 8];
            float ea0 = fmaxf(E0.x * Ed.x, E0.y * Ed.y);
            z += ea0;
            __half2* p0 = (__half2*)&hv0;
#pragma unroll
            for (int q = 0; q < 4; q++) {
                float2 f0 = __half22float2(p0[q]);
                acc[2 * q]     += ea0 * f0.x;
                acc[2 * q + 1] += ea0 * f0.y;
            }
        }
    }
    float inv = 1.f / (z + 1e-16f);

    float x1[8];
    float4 bA = *(const float4*)&b1[lane * 8];
    float4 bB = *(const float4*)&b1[lane * 8 + 4];
    float bb[8] = {bA.x, bA.y, bA.z, bA.w, bB.x, bB.y, bB.z, bB.w};
#pragma unroll
    for (int j = 0; j < 8; j++) {
        float v = acc[j] * inv + bb[j];
        x1[j] = v > 0.f ? v : expm1f(v);
    }

    float p[8];
#pragma unroll
    for (int o = 0; o < 8; o++) p[o] = 0.f;
#pragma unroll
    for (int j = 0; j < 8; j++) {
        int c = lane * 8 + j;
        float4 w0 = *(const float4*)&W2[c * 8];
        float4 w1 = *(const float4*)&W2[c * 8 + 4];
        p[0] += x1[j] * w0.x; p[1] += x1[j] * w0.y;
        p[2] += x1[j] * w0.z; p[3] += x1[j] * w0.w;
        p[4] += x1[j] * w1.x; p[5] += x1[j] * w1.y;
        p[6] += x1[j] * w1.z; p[7] += x1[j] * w1.w;
    }
#pragma unroll
    for (int o = 0; o < 8; o++)
#pragma unroll
        for (int k = 16; k > 0; k >>= 1) p[o] += __shfl_xor_sync(~0u, p[o], k);

    float s2 = 0.f, d2 = 0.f;
#pragma unroll
    for (int o = 0; o < 8; o++) { s2 += p[o] * as2[o]; d2 += p[o] * ad2[o]; }
    if (lane == 0) {
        g_P[d] = make_float2(__expf(s2), __expf(0.2f * s2));
        g_Q[d] = make_float2(__expf(d2), __expf(0.2f * d2));
        *(float4*)&g_h2[d * 8]     = make_float4(p[0], p[1], p[2], p[3]);
        *(float4*)&g_h2[d * 8 + 4] = make_float4(p[4], p[5], p[6], p[7]);
        g_cnt[d] = 0;   // reset for next replay
    }
}

// ---------------- launch 6: layer-2 aggregation + log_softmax ----------------
__global__ void __launch_bounds__(256) k_agg2(const float* __restrict__ b2,
                                              float* __restrict__ out) {
    int d = (blockIdx.x * blockDim.x + threadIdx.x) >> 5;
    int lane = threadIdx.x & 31;
    if (d >= NN) return;
    int2 seg = g_seg[d];
    int beg = seg.x, end = seg.y;
    float2 q = g_Q[d];

    float z = 0.f, acc[8];
#pragma unroll
    for (int o = 0; o < 8; o++) acc[o] = 0.f;
    for (int e = beg + lane; e < end; e += 32) {
        int s = g_csr[e];
        float2 P = g_P[s];
        float ea = fmaxf(P.x * q.x, P.y * q.y);
        z += ea;
        const float4* hp = (const float4*)&g_h2[s * 8];
        float4 v0 = hp[0], v1 = hp[1];
        acc[0] += ea * v0.x; acc[1] += ea * v0.y; acc[2] += ea * v0.z; acc[3] += ea * v0.w;
        acc[4] += ea * v1.x; acc[5] += ea * v1.y; acc[6] += ea * v1.z; acc[7] += ea * v1.w;
    }
#pragma unroll
    for (int k = 16; k > 0; k >>= 1) z += __shfl_xor_sync(~0u, z, k);
#pragma unroll
    for (int o = 0; o < 8; o++)
#pragma unroll
        for (int k = 16; k > 0; k >>= 1) acc[o] += __shfl_xor_sync(~0u, acc[o], k);

    float inv = 1.f / (z + 1e-16f);
    float v[8], mx = -1e30f;
#pragma unroll
    for (int o = 0; o < 8; o++) { v[o] = acc[o] * inv + b2[o]; mx = fmaxf(mx, v[o]); }
    float se = 0.f;
#pragma unroll
    for (int o = 0; o < 8; o++) se += expf(v[o] - mx);
    float lse = mx + logf(se);
    if (lane == 0) {
        *(float4*)&out[d * 8]     = make_float4(v[0] - lse, v[1] - lse, v[2] - lse, v[3] - lse);
        *(float4*)&out[d * 8 + 4] = make_float4(v[4] - lse, v[5] - lse, v[6] - lse, v[7] - lse);
    }
}

// ---------------- launch ----------------
extern "C" void kernel_launch(void* const* d_in, const int* in_sizes, int n_in,
                              void* d_out, int out_size) {
    const float* high  = (const float*)d_in[0];
    const float* low   = (const float*)d_in[1];
    const int*   ei    = (const int*)d_in[2];
    const float* Wemb  = (const float*)d_in[3];
    const float* bemb  = (const float*)d_in[4];
    const float* W1    = (const float*)d_in[5];
    const float* asrc1 = (const float*)d_in[6];
    const float* adst1 = (const float*)d_in[7];
    const float* b1    = (const float*)d_in[8];
    const float* W2    = (const float*)d_in[9];
    const float* as2   = (const float*)d_in[10];
    const float* ad2   = (const float*)d_in[11];
    const float* b2    = (const float*)d_in[12];
    float* out = (float*)d_out;

    cudaFuncSetAttribute(k_gemm, cudaFuncAttributeMaxDynamicSharedMemorySize, SMEM_B);

    dim3 fb(192, 2);
    k_front<<<EMB_B + EDGE_B + W1T_B, fb>>>(high, low, Wemb, bemb, W1, ei);   // 1
    k_scan<<<1, 1024>>>();                                                    // 2
    k_scatter<<<(EE + 255) / 256, 256>>>(ei);                                 // 3
    dim3 gg((NN + 127) / 128, 2);
    k_gemm<<<gg, 256, SMEM_B>>>(asrc1, adst1);                                // 4 <- ncu
    k_agg1<<<(NN + 7) / 8, 256>>>(b1, W2, as2, ad2);                          // 5
    k_agg2<<<(NN + 7) / 8, 256>>>(b2, out);                                   // 6
}